// round 17
// baseline (speedup 1.0000x reference)
#include <cuda_runtime.h>
#include <cstdint>
#include <math.h>

#define T_FRAMES 1001
#define BATCH    16
#define LSIG     240000
#define HOP      240
#define DIN      301
#define HID      128
#define DOUTN    64
#define NROWS    (T_FRAMES*BATCH)   // 16016

typedef unsigned long long ull;
typedef unsigned int u32;

// ------------------------- static device scratch -------------------------
__device__ float2 g_tw[1024];                  // twiddles e^{-2pi i k/2048}
__device__ float  g_feat[NROWS * DIN];         // features [row=t*16+b][301]
__device__ float  g_wihT[DIN * 1024];          // transposed input weights [k][g]
__device__ float  g_bias[1024];
__device__ float  g_pre[NROWS * 1024];         // pre-activations [row][1024]
__device__ float2 g_whhP[2 * 64 * 512];        // [d][k2][g] = (W[g][2k2], W[g][2k2+1])
__device__ float  g_hcat[NROWS * 256];         // [row][fwd 0..127 | bwd 128..255]
__device__ float  g_owT[256 * 64];             // out_w transposed [k][o]

// ------------------------------ prep kernel ------------------------------
__global__ void prep_kernel(const float* __restrict__ wihf, const float* __restrict__ whhf,
                            const float* __restrict__ bf,   const float* __restrict__ wihb,
                            const float* __restrict__ whhb, const float* __restrict__ bb,
                            const float* __restrict__ outw)
{
    int tid = blockIdx.x * blockDim.x + threadIdx.x;
    int nth = gridDim.x * blockDim.x;

    for (int k = tid; k < 1024; k += nth) {
        float s, c;
        sincospif((float)k * (1.0f/1024.0f), &s, &c);
        g_tw[k] = make_float2(c, -s);
    }
    for (int i = tid; i < DIN*1024; i += nth) {
        int g = i & 1023, k = i >> 10;
        g_wihT[i] = (g < 512) ? wihf[g*DIN + k] : wihb[(g-512)*DIN + k];
    }
    for (int g = tid; g < 1024; g += nth)
        g_bias[g] = (g < 512) ? bf[g] : bb[g-512];
    for (int i = tid; i < 2*64*512; i += nth) {
        int d = i >> 15;
        int k2 = (i >> 9) & 63;
        int g = i & 511;
        const float* W = d ? whhb : whhf;
        g_whhP[i] = make_float2(W[g*HID + 2*k2], W[g*HID + 2*k2 + 1]);
    }
    for (int i = tid; i < 256*64; i += nth) {
        int o = i & 63, k = i >> 6;
        g_owT[i] = outw[o*256 + k];
    }
}

// ---------------------- STFT (real-packed) + features ---------------------
__device__ __forceinline__ float wsamp(const float* __restrict__ xb, int t, int j)
{
    int q = t*HOP + j - 1024;
    if (q < 0) q = -q;
    else if (q >= LSIG) q = 2*LSIG - 2 - q;
    int jw = j - 544;
    float wv = (jw >= 0 && jw < 960) ? (0.5f - 0.5f*cospif((float)jw * (1.0f/480.0f))) : 0.0f;
    return xb[q] * wv;
}

__global__ __launch_bounds__(256) void stft_kernel(const float* __restrict__ x,
                                                   const float* __restrict__ f0)
{
    __shared__ float2 S[1024];
    int t = blockIdx.x, b = blockIdx.y, tid = threadIdx.x;
    const float* xb = x + b * LSIG;

    for (int n = tid; n < 1024; n += 256) {
        float v0 = wsamp(xb, t, 2*n);
        float v1 = wsamp(xb, t, 2*n + 1);
        int rev = __brev((unsigned)n) >> 22;
        S[rev] = make_float2(v0, v1);
    }
    __syncthreads();

    #pragma unroll
    for (int s = 1; s <= 10; s++) {
        int half = 1 << (s-1);
        for (int idx = tid; idx < 512; idx += 256) {
            int pos = idx & (half - 1);
            int grp = idx >> (s-1);
            int i0 = (grp << s) + pos;
            int i1 = i0 + half;
            float2 tw = g_tw[pos << (11 - s)];
            float2 u = S[i0], v = S[i1];
            float tr = tw.x*v.x - tw.y*v.y;
            float ti = tw.x*v.y + tw.y*v.x;
            S[i0] = make_float2(u.x + tr, u.y + ti);
            S[i1] = make_float2(u.x - tr, u.y - ti);
        }
        __syncthreads();
    }

    float f0v = f0[b*T_FRAMES + t];
    float f0nz = (f0v > 0.0f) ? f0v : 80.0f;
    int rowbase = (t*BATCH + b) * DIN;
    for (int j = tid; j < 300; j += 256) {
        float m = 0.5f * (float)(j + 1);
        float harm = f0nz * m;
        float r = harm / 11.71875f;
        int k = (int)rintf(r);
        k = min(max(k, 0), 1024);
        float p = 0.0f;
        if (k < 1024) {
            int kr = (1024 - k) & 1023;
            float2 a = S[k];
            float2 zr = S[kr];
            float br = zr.x, bi = -zr.y;
            float xer = 0.5f*(a.x + br), xei = 0.5f*(a.y + bi);
            float dr = a.x - br, di = a.y - bi;
            float xo_r = 0.5f*di, xo_i = -0.5f*dr;
            float sn, cs;
            sincospif((float)k * (1.0f/1024.0f), &sn, &cs);
            float wr = cs, wi = -sn;
            float Xr = xer + wr*xo_r - wi*xo_i;
            float Xi = xei + wr*xo_i + wi*xo_r;
            p = Xr*Xr + Xi*Xi;
        }
        g_feat[rowbase + j] = (logf(p + 1e-8f) + 18.0f) / 23.0f;
    }
    if (tid == 0) g_feat[rowbase + 300] = logf(f0nz);
}

// ---------------------------- input pre-GEMM ------------------------------
__global__ __launch_bounds__(256) void pre_gemm_kernel()
{
    __shared__ float s_feat[16 * DIN];
    int t = blockIdx.x;
    int cb = blockIdx.y * 512;
    int tid = threadIdx.x;

    int base = t * 16 * DIN;
    for (int i = tid; i < 16*DIN; i += 256) s_feat[i] = g_feat[base + i];
    __syncthreads();

    int cl = (tid & 127) * 4 + cb;
    int rh = tid >> 7;
    float4 acc[8];
    float4 bias = *(const float4*)&g_bias[cl];
    #pragma unroll
    for (int r = 0; r < 8; r++) acc[r] = bias;

    const float* fb = s_feat + rh*8*DIN;
    for (int k = 0; k < DIN; k++) {
        float4 w = *(const float4*)&g_wihT[k*1024 + cl];
        #pragma unroll
        for (int r = 0; r < 8; r++) {
            float f = fb[r*DIN + k];
            acc[r].x += f*w.x; acc[r].y += f*w.y; acc[r].z += f*w.z; acc[r].w += f*w.w;
        }
    }
    #pragma unroll
    for (int r = 0; r < 8; r++) {
        int row = t*16 + rh*8 + r;
        *(float4*)&g_pre[row*1024 + cl] = acc[r];
    }
}

// ------------------------------ bi-LSTM ----------------------------------
__device__ __forceinline__ float fsigm(float x) {
    float e = __expf(-fabsf(x));
    float inv = __fdividef(1.0f, 1.0f + e);
    return (x >= 0.0f) ? inv : e * inv;
}
__device__ __forceinline__ float ftanh(float x) {
    float e = __expf(-2.0f * fabsf(x));
    float r = __fdividef(1.0f - e, 1.0f + e);
    return copysignf(r, x);
}
__device__ __forceinline__ ull ffma2(ull a, ull b, ull c) {
    ull d;
    asm("fma.rn.f32x2 %0, %1, %2, %3;" : "=l"(d) : "l"(a), "l"(b), "l"(c));
    return d;
}
__device__ __forceinline__ float2 u2f2(ull a) {
    float2 f;
    asm("mov.b64 {%0, %1}, %2;" : "=f"(f.x), "=f"(f.y) : "l"(a));
    return f;
}
#define CLUSTER_SYNC() do { \
    asm volatile("barrier.cluster.arrive.aligned;" ::: "memory"); \
    asm volatile("barrier.cluster.wait.aligned;"   ::: "memory"); \
} while (0)

// cluster of 4 CTAs per (d, batch-PAIR). Rank r owns h rows [32r,32r+32) for
// BOTH batches (same d => same W_hh => same weight registers). Per step the
// cluster interleaves: waitA/dotA/gatesA/shipA then waitB/dotB/gatesB/shipB —
// job A's DSMEM flight is hidden behind job B's compute and vice versa.
// hbuf[job][par][src_rank][32]; 4 parity mbarriers (job*2+par), each expecting
// 3 peers x 128B = 384B per step. Per-job math identical to the 1-job version.
__global__ __launch_bounds__(512, 1) __cluster_dims__(4, 1, 1)
void lstm_kernel()
{
    int cid  = blockIdx.x >> 2;      // 0..15
    int rank = blockIdx.x & 3;       // h-row quarter owned
    int d  = cid >> 3;               // direction
    int bp = cid & 7;                // batch pair
    int bA = bp*2, bB = bp*2 + 1;
    int tid = threadIdx.x;
    int u  = tid >> 7;               // k-quarter this thread computes (0..3)
    int rl = tid & 127;              // local gate row = q*32 + j
    int q  = rl >> 5;
    int j  = rl & 31;
    int grow = q*128 + rank*32 + j;  // global W row

    // 32 weights (k in [32u,32u+32)) as 16 packed f32x2 — shared by both jobs
    ull w2[16];
    {
        const ull* WP = (const ull*)g_whhP + ((size_t)d*64 + 16*u)*512 + grow;
        #pragma unroll
        for (int jj = 0; jj < 16; jj++) w2[jj] = WP[jj*512];
    }

    __shared__ __align__(16) float hbuf[2][2][4][32];  // [job][par][src][row]
    __shared__ float part_sh[2][512];                  // [job][u*128 + rl]
    __shared__ __align__(8) ull s_bar[4];              // [job*2 + par]

    ((float*)hbuf)[tid] = 0.0f;                        // 512 floats total
    u32 bar_local  = (u32)__cvta_generic_to_shared(s_bar);
    u32 hbuf_local = (u32)__cvta_generic_to_shared(hbuf);
    if (tid == 0) {
        #pragma unroll
        for (int i = 0; i < 4; i++) {
            asm volatile("mbarrier.init.shared.b64 [%0], 1;" :: "r"(bar_local + 8u*i) : "memory");
            asm volatile("mbarrier.arrive.expect_tx.shared.b64 _, [%0], %1;"
                         :: "r"(bar_local + 8u*i), "r"(384u) : "memory");
        }
    }
    float c_state = 0.0f;
    __syncthreads();
    CLUSTER_SYNC();   // all ranks' barriers armed before any st.async

    u32 hbuf_all[4], bar_all[4];
    #pragma unroll
    for (int pr = 0; pr < 4; pr++) {
        asm("mapa.shared::cluster.u32 %0, %1, %2;" : "=r"(hbuf_all[pr]) : "r"(hbuf_local), "r"((u32)pr));
        asm("mapa.shared::cluster.u32 %0, %1, %2;" : "=r"(bar_all[pr])  : "r"(bar_local),  "r"((u32)pr));
    }

    const float* preB_ = g_pre + d*512;
    float* hcatP = g_hcat + d*HID + rank*32;

    // gate role: tid<32 -> job A rows, tid in [32,64) -> job B rows
    int gjob = (tid < 32) ? 0 : ((tid < 64) ? 1 : -1);
    int gj = tid & 31;               // gate row within this CTA's quarter
    int jglob = rank*32 + gj;
    int bg = (gjob == 0) ? bA : bB;

    // prologue: deliver h0 = 0 for step 0 (parity 0), both jobs
    if (gjob >= 0) {
        u32 doff = (u32)gjob*1024u + (u32)rank*128u + (u32)gj*4u;   // [job][0][rank][gj]
        u32 bofs = 8u*((u32)gjob*2u);
        #pragma unroll
        for (int pr = 0; pr < 4; pr++) if (pr != rank) {
            asm volatile("st.async.shared::cluster.mbarrier::complete_tx::bytes.b32 [%0], %1, [%2];"
                         :: "r"(hbuf_all[pr] + doff), "r"(0u), "r"(bar_all[pr] + bofs) : "memory");
        }
    }

    // prefetch pre-activations for step 0 (gate threads only)
    float pn0 = 0.f, pn1 = 0.f, pn2 = 0.f, pn3 = 0.f;
    if (gjob >= 0) {
        int t0 = d ? (T_FRAMES - 1) : 0;
        const float* pr = preB_ + (size_t)(t0*BATCH + bg)*1024 + jglob;
        pn0 = pr[0]; pn1 = pr[128]; pn2 = pr[256]; pn3 = pr[384];
    }

    bool iswait = (u != rank);
    int rearm_tid = (rank == 0) ? 128 : 0;   // a wait-quarter thread
    for (int s = 0; s < T_FRAMES; s++) {
        int t = d ? (T_FRAMES - 1 - s) : s;
        u32 par = (u32)(s & 1);
        u32 ph  = (u32)((s >> 1) & 1);

        float p0 = pn0, p1 = pn1, p2 = pn2, p3 = pn3;
        if (gjob >= 0 && s + 1 < T_FRAMES) {
            int tn = d ? (T_FRAMES - 2 - s) : (s + 1);
            const float* pr = preB_ + (size_t)(tn*BATCH + bg)*1024 + jglob;
            pn0 = pr[0]; pn1 = pr[128]; pn2 = pr[256]; pn3 = pr[384];
        }

        // ======== JOB A ========
        if (iswait) {
            asm volatile("{\n\t"
                         ".reg .pred P;\n"
                         "LWA%=:\n\t"
                         "mbarrier.try_wait.parity.acquire.cta.shared::cta.b64 P, [%0], %1, 0x989680;\n\t"
                         "@!P bra LWA%=;\n\t"
                         "}" :: "r"(bar_local + 8u*par), "r"(ph) : "memory");
            if (tid == rearm_tid && s + 2 < T_FRAMES) {
                asm volatile("mbarrier.arrive.expect_tx.shared.b64 _, [%0], %1;"
                             :: "r"(bar_local + 8u*par), "r"(384u) : "memory");
            }
        }
        {
            const ulonglong2* hh = (const ulonglong2*)hbuf[0][par][u];
            ull a0 = 0ULL, a1 = 0ULL, a2 = 0ULL, a3 = 0ULL;
            #pragma unroll
            for (int jj = 0; jj < 4; jj++) {
                ulonglong2 hA = hh[2*jj], hB = hh[2*jj+1];
                a0 = ffma2(w2[4*jj+0], hA.x, a0);
                a1 = ffma2(w2[4*jj+1], hA.y, a1);
                a2 = ffma2(w2[4*jj+2], hB.x, a2);
                a3 = ffma2(w2[4*jj+3], hB.y, a3);
            }
            float2 f0v = u2f2(a0), f1v = u2f2(a1), f2v = u2f2(a2), f3v = u2f2(a3);
            part_sh[0][tid] = ((f0v.x + f0v.y) + (f1v.x + f1v.y))
                            + ((f2v.x + f2v.y) + (f3v.x + f3v.y));
        }
        __syncthreads();
        if (gjob == 0) {
            const float* ps = part_sh[0];
            float zi = ((ps[gj]    + ps[128+gj]) + (ps[256+gj] + ps[384+gj])) + p0;
            float zf = ((ps[32+gj] + ps[160+gj]) + (ps[288+gj] + ps[416+gj])) + p1;
            float zg = ((ps[64+gj] + ps[192+gj]) + (ps[320+gj] + ps[448+gj])) + p2;
            float zo = ((ps[96+gj] + ps[224+gj]) + (ps[352+gj] + ps[480+gj])) + p3;
            c_state = fsigm(zf)*c_state + fsigm(zi)*ftanh(zg);
            float h = fsigm(zo)*ftanh(c_state);
            hbuf[0][par^1][rank][gj] = h;
            hcatP[(size_t)(t*BATCH + bA)*256 + gj] = h;
            if (s + 1 < T_FRAMES) {
                u32 v = __float_as_uint(h);
                u32 doff = (par^1u)*512u + (u32)rank*128u + (u32)gj*4u;   // job 0
                u32 bofs = 8u*(par^1u);
                #pragma unroll
                for (int pr = 0; pr < 4; pr++) if (pr != rank) {
                    asm volatile("st.async.shared::cluster.mbarrier::complete_tx::bytes.b32 [%0], %1, [%2];"
                                 :: "r"(hbuf_all[pr] + doff), "r"(v),
                                    "r"(bar_all[pr] + bofs) : "memory");
                }
            }
        }

        // ======== JOB B ========
        if (iswait) {
            asm volatile("{\n\t"
                         ".reg .pred P;\n"
                         "LWB%=:\n\t"
                         "mbarrier.try_wait.parity.acquire.cta.shared::cta.b64 P, [%0], %1, 0x989680;\n\t"
                         "@!P bra LWB%=;\n\t"
                         "}" :: "r"(bar_local + 16u + 8u*par), "r"(ph) : "memory");
            if (tid == rearm_tid && s + 2 < T_FRAMES) {
                asm volatile("mbarrier.arrive.expect_tx.shared.b64 _, [%0], %1;"
                             :: "r"(bar_local + 16u + 8u*par), "r"(384u) : "memory");
            }
        }
        {
            const ulonglong2* hh = (const ulonglong2*)hbuf[1][par][u];
            ull a0 = 0ULL, a1 = 0ULL, a2 = 0ULL, a3 = 0ULL;
            #pragma unroll
            for (int jj = 0; jj < 4; jj++) {
                ulonglong2 hA = hh[2*jj], hB = hh[2*jj+1];
                a0 = ffma2(w2[4*jj+0], hA.x, a0);
                a1 = ffma2(w2[4*jj+1], hA.y, a1);
                a2 = ffma2(w2[4*jj+2], hB.x, a2);
                a3 = ffma2(w2[4*jj+3], hB.y, a3);
            }
            float2 f0v = u2f2(a0), f1v = u2f2(a1), f2v = u2f2(a2), f3v = u2f2(a3);
            part_sh[1][tid] = ((f0v.x + f0v.y) + (f1v.x + f1v.y))
                            + ((f2v.x + f2v.y) + (f3v.x + f3v.y));
        }
        __syncthreads();
        if (gjob == 1) {
            const float* ps = part_sh[1];
            float zi = ((ps[gj]    + ps[128+gj]) + (ps[256+gj] + ps[384+gj])) + p0;
            float zf = ((ps[32+gj] + ps[160+gj]) + (ps[288+gj] + ps[416+gj])) + p1;
            float zg = ((ps[64+gj] + ps[192+gj]) + (ps[320+gj] + ps[448+gj])) + p2;
            float zo = ((ps[96+gj] + ps[224+gj]) + (ps[352+gj] + ps[480+gj])) + p3;
            c_state = fsigm(zf)*c_state + fsigm(zi)*ftanh(zg);
            float h = fsigm(zo)*ftanh(c_state);
            hbuf[1][par^1][rank][gj] = h;
            hcatP[(size_t)(t*BATCH + bB)*256 + gj] = h;
            if (s + 1 < T_FRAMES) {
                u32 v = __float_as_uint(h);
                u32 doff = 1024u + (par^1u)*512u + (u32)rank*128u + (u32)gj*4u;  // job 1
                u32 bofs = 16u + 8u*(par^1u);
                #pragma unroll
                for (int pr = 0; pr < 4; pr++) if (pr != rank) {
                    asm volatile("st.async.shared::cluster.mbarrier::complete_tx::bytes.b32 [%0], %1, [%2];"
                                 :: "r"(hbuf_all[pr] + doff), "r"(v),
                                    "r"(bar_all[pr] + bofs) : "memory");
                }
            }
        }
        __syncthreads();   // both jobs' local h slots visible for next step
    }
    CLUSTER_SYNC();        // no CTA exits with peer traffic in flight
}

// ----------------------- LayerNorm + output GEMM --------------------------
__global__ __launch_bounds__(256) void final_kernel(const float* __restrict__ ln_g,
                                                    const float* __restrict__ ln_b,
                                                    const float* __restrict__ out_b,
                                                    float* __restrict__ out)
{
    __shared__ float sh[16*256];
    __shared__ float s_sum[256], s_sq[256];
    __shared__ float s_mu[16], s_rstd[16];

    int t = blockIdx.x, tid = threadIdx.x;
    for (int i = tid; i < 4096; i += 256) sh[i] = g_hcat[t*4096 + i];
    __syncthreads();

    {
        int row = tid >> 4, seg = tid & 15;
        float sm = 0.f, sq = 0.f;
        const float* p = sh + row*256 + seg*16;
        #pragma unroll
        for (int u = 0; u < 16; u++) { float v = p[u]; sm += v; sq += v*v; }
        s_sum[tid] = sm; s_sq[tid] = sq;
    }
    __syncthreads();
    if (tid < 16) {
        float sm = 0.f, sq = 0.f;
        #pragma unroll
        for (int u = 0; u < 16; u++) { sm += s_sum[tid*16 + u]; sq += s_sq[tid*16 + u]; }
        float mu = sm * (1.0f/256.0f);
        float var = sq * (1.0f/256.0f) - mu*mu;
        s_mu[tid] = mu;
        s_rstd[tid] = rsqrtf(var + 1e-5f);
    }
    __syncthreads();
    for (int i = tid; i < 4096; i += 256) {
        int r = i >> 8, k = i & 255;
        sh[i] = (sh[i] - s_mu[r]) * s_rstd[r] * ln_g[k] + ln_b[k];
    }
    __syncthreads();

    int col = tid & 63, rg = tid >> 6;
    float acc[4];
    float bb = out_b[col];
    #pragma unroll
    for (int r = 0; r < 4; r++) acc[r] = bb;
    for (int k = 0; k < 256; k++) {
        float w = g_owT[k*64 + col];
        #pragma unroll
        for (int r = 0; r < 4; r++) acc[r] += sh[(rg*4 + r)*256 + k] * w;
    }
    #pragma unroll
    for (int r = 0; r < 4; r++) {
        int b = rg*4 + r;
        out[(b*T_FRAMES + t)*DOUTN + col] = acc[r];
    }
}

// ------------------------------ launcher ----------------------------------
extern "C" void kernel_launch(void* const* d_in, const int* in_sizes, int n_in,
                              void* d_out, int out_size)
{
    const float* x     = (const float*)d_in[0];
    const float* f0    = (const float*)d_in[1];
    const float* wihf  = (const float*)d_in[2];
    const float* whhf  = (const float*)d_in[3];
    const float* bf    = (const float*)d_in[4];
    const float* wihb  = (const float*)d_in[5];
    const float* whhb  = (const float*)d_in[6];
    const float* bb    = (const float*)d_in[7];
    const float* lng   = (const float*)d_in[8];
    const float* lnb   = (const float*)d_in[9];
    const float* outw  = (const float*)d_in[10];
    const float* outb  = (const float*)d_in[11];
    float* out = (float*)d_out;

    prep_kernel<<<256, 256>>>(wihf, whhf, bf, wihb, whhb, bb, outw);
    stft_kernel<<<dim3(T_FRAMES, BATCH), 256>>>(x, f0);
    pre_gemm_kernel<<<dim3(T_FRAMES, 2), 256>>>();
    lstm_kernel<<<64, 512>>>();
    final_kernel<<<T_FRAMES, 256>>>(lng, lnb, outb, out);
}